// round 15
// baseline (speedup 1.0000x reference)
#include <cuda_runtime.h>
#include <cuda_bf16.h>
#include <cstdint>

// S4D diagonal SSM via split-precision bf16 mma.sync (HMMA).
// Factor l = 64k + j (k in [0,32), j in [0,64)):
//   out[h,64k+j] = sum_n ( Bre[k,n]*Are[n,j] - Bim[k,n]*Aim[n,j] )
// GEMM: D2[64][64] = Bop[64x128] . Aop[64x128]^T,  reduction dim = 2n (re,im)
//   Bop rows 0-31 = bf16_hi(Bre,-Bim), rows 32-63 = bf16_lo residual.
//   A hi/lo tables = accumulating passes; B-lo rows take only the A-hi pass
//   (dropped Bl*Al term ~2^-18). out[64k+j] = D2[k][j] + D2[k+32][j] in registers.
// R15: 256 thr/block (8 warps) -> phase-1 chains halved, 32 warps/SM; MMA -25%.

#define HDIM 1024
#define NDIM 64
#define LLEN 2048

#define ROWB 272      // row stride bytes: 128 bf16 + 8 pad (68 words = 4 mod 32)
#define SM_BOP 0                      // 64 x ROWB
#define SM_AH  (64*ROWB)
#define SM_AL  (SM_AH + 64*ROWB)
#define SM_TOTAL (SM_AL + 64*ROWB)    // 52224 B

struct c2 { float re, im; };
__device__ __forceinline__ c2 cmul(c2 a, c2 b) {
    return { fmaf(a.re, b.re, -a.im*b.im), fmaf(a.re, b.im, a.im*b.re) };
}

__device__ __forceinline__ void mma16816(float* c, const uint32_t* a, const uint32_t* b) {
    asm volatile(
        "mma.sync.aligned.m16n8k16.row.col.f32.bf16.bf16.f32 "
        "{%0,%1,%2,%3}, {%4,%5,%6,%7}, {%8,%9}, {%0,%1,%2,%3};"
        : "+f"(c[0]), "+f"(c[1]), "+f"(c[2]), "+f"(c[3])
        : "r"(a[0]), "r"(a[1]), "r"(a[2]), "r"(a[3]), "r"(b[0]), "r"(b[1]));
}

__global__ __launch_bounds__(256) void ssk_diag_kernel(
    const float* __restrict__ log_dt,
    const float* __restrict__ log_w_real,
    const float* __restrict__ w_imag,
    const float* __restrict__ C_re,
    const float* __restrict__ C_im,
    float* __restrict__ out)
{
    extern __shared__ char smem[];
    const int h   = blockIdx.x;
    const int tid = threadIdx.x;
    const int wid = tid >> 5;
    const int lid = tid & 31;

    // ------------- Phase 1: tables. tid = q*64 + n (4 segments per n) ---------------
    {
        const int n = tid & 63;
        const int q = tid >> 6;     // 0..3

        const float dtv = expf(log_dt[h]);
        const float wre = -expf(log_w_real[h*NDIM + n]);
        const float wim = w_imag[h*NDIM + n];
        const float er  = expf(wre * dtv);
        float s, c; sincosf(wim * dtv, &s, &c);
        const c2 z = { er*c, er*s };

        // cmod = 2 * C * (z - 1) / w  (fold the output factor of 2)
        const float nre = z.re - 1.0f, nim = z.im;
        const float inv = 1.0f / (wre*wre + wim*wim);
        const float tre = (nre*wre + nim*wim) * inv;
        const float tim = (nim*wre - nre*wim) * inv;
        const float cr = C_re[h*NDIM + n], ci = C_im[h*NDIM + n];
        const c2 cm = { 2.0f*(cr*tre - ci*tim), 2.0f*(cr*tim + ci*tre) };

        // power ladder by squaring
        const c2 z2    = cmul(z,    z);
        const c2 z4    = cmul(z2,   z2);
        const c2 z8    = cmul(z4,   z4);
        const c2 z16   = cmul(z8,   z8);
        const c2 z32   = cmul(z16,  z16);
        const c2 z64   = cmul(z32,  z32);
        const c2 z128  = cmul(z64,  z64);
        const c2 z256  = cmul(z128, z128);
        const c2 z512  = cmul(z256, z256);
        const c2 z1024 = cmul(z512, z512);

        // Aop: rows j = 16q .. 16q+15, cols (2n,2n+1) = (Are, Aim); hi + lo residual
        c2 a = {1.0f, 0.0f};
        if (q & 1) a = z16;
        if (q & 2) a = cmul(a, z32);
        #pragma unroll
        for (int jj = 0; jj < 16; jj++) {
            const int j = 16*q + jj;
            const __nv_bfloat16 hr = __float2bfloat16_rn(a.re);
            const __nv_bfloat16 hi = __float2bfloat16_rn(a.im);
            *reinterpret_cast<__nv_bfloat162*>(smem + SM_AH + j*ROWB + 4*n) =
                __nv_bfloat162(hr, hi);
            *reinterpret_cast<__nv_bfloat162*>(smem + SM_AL + j*ROWB + 4*n) =
                __floats2bfloat162_rn(a.re - __bfloat162float(hr),
                                      a.im - __bfloat162float(hi));
            a = cmul(a, z);
        }

        // Bop: rows k = 8q .. 8q+7 (hi) and k+32 (lo), cols = (Bre, -Bim)
        c2 b = cm;
        if (q & 1) b = cmul(b, z512);
        if (q & 2) b = cmul(b, z1024);
        #pragma unroll
        for (int kk = 0; kk < 8; kk++) {
            const int k = 8*q + kk;
            const float bre = b.re, bim = -b.im;
            const __nv_bfloat16 hr = __float2bfloat16_rn(bre);
            const __nv_bfloat16 hi = __float2bfloat16_rn(bim);
            *reinterpret_cast<__nv_bfloat162*>(smem + SM_BOP + k*ROWB + 4*n) =
                __nv_bfloat162(hr, hi);
            *reinterpret_cast<__nv_bfloat162*>(smem + SM_BOP + (k+32)*ROWB + 4*n) =
                __floats2bfloat162_rn(bre - __bfloat162float(hr),
                                      bim - __bfloat162float(hi));
            b = cmul(b, z64);
        }
    }
    __syncthreads();

    // ------------- Phase 2: mma.sync. 8 warps: mw = wid&1, nw = wid>>1 -------------
    // M-side (Bop): rows 16mw (hi) and 16mw+32 (lo).
    // N-side (Aop): 2 n8 tiles covering j = 16nw .. 16nw+15.
    const int g  = lid >> 2;    // 0..7
    const int t  = lid & 3;     // 0..3
    const int mw = wid & 1;
    const int nw = wid >> 1;    // 0..3

    float acc[2][2][4];         // [mt][nt][c]
    #pragma unroll
    for (int mt = 0; mt < 2; mt++)
        #pragma unroll
        for (int nt = 0; nt < 2; nt++)
            #pragma unroll
            for (int i = 0; i < 4; i++) acc[mt][nt][i] = 0.0f;

    #pragma unroll
    for (int s = 0; s < 8; s++) {
        const int kb0 = (16*s + 2*t) * 2;
        const int kb1 = (16*s + 2*t + 8) * 2;

        uint32_t af[2][4];
        #pragma unroll
        for (int mt = 0; mt < 2; mt++) {
            const int r = 16*mw + 32*mt + g;
            af[mt][0] = *reinterpret_cast<const uint32_t*>(smem + SM_BOP + r*ROWB     + kb0);
            af[mt][1] = *reinterpret_cast<const uint32_t*>(smem + SM_BOP + (r+8)*ROWB + kb0);
            af[mt][2] = *reinterpret_cast<const uint32_t*>(smem + SM_BOP + r*ROWB     + kb1);
            af[mt][3] = *reinterpret_cast<const uint32_t*>(smem + SM_BOP + (r+8)*ROWB + kb1);
        }
        uint32_t bh[2][2], bl[2][2];
        #pragma unroll
        for (int nt = 0; nt < 2; nt++) {
            const int j = 16*nw + 8*nt + g;
            bh[nt][0] = *reinterpret_cast<const uint32_t*>(smem + SM_AH + j*ROWB + kb0);
            bh[nt][1] = *reinterpret_cast<const uint32_t*>(smem + SM_AH + j*ROWB + kb1);
            bl[nt][0] = *reinterpret_cast<const uint32_t*>(smem + SM_AL + j*ROWB + kb0);
            bl[nt][1] = *reinterpret_cast<const uint32_t*>(smem + SM_AL + j*ROWB + kb1);
        }

        #pragma unroll
        for (int nt = 0; nt < 2; nt++) {
            mma16816(acc[0][nt], af[0], bh[nt]);   // Bh * Ah
            mma16816(acc[0][nt], af[0], bl[nt]);   // Bh * Al
            mma16816(acc[1][nt], af[1], bh[nt]);   // Bl * Ah  (Bl*Al dropped, ~2^-18)
        }
    }

    // ------------- Epilogue: in-register halves add, direct STG.64 ------------------
    // Thread owns D2 rows k = 16mw+g, +8 (hi) and +32 (lo); cols j = 16nw+8nt+2t,+1.
    {
        const int k0 = 16*mw + g;
        float* po = out + (size_t)h*LLEN + 16*nw + 2*t;
        #pragma unroll
        for (int nt = 0; nt < 2; nt++) {
            float2 v0, v1;
            v0.x = acc[0][nt][0] + acc[1][nt][0];
            v0.y = acc[0][nt][1] + acc[1][nt][1];
            v1.x = acc[0][nt][2] + acc[1][nt][2];
            v1.y = acc[0][nt][3] + acc[1][nt][3];
            *reinterpret_cast<float2*>(po + (size_t)k0*64 + 8*nt)     = v0;
            *reinterpret_cast<float2*>(po + (size_t)(k0+8)*64 + 8*nt) = v1;
        }
    }
}

extern "C" void kernel_launch(void* const* d_in, const int* in_sizes, int n_in,
                              void* d_out, int out_size)
{
    const float* log_dt     = (const float*)d_in[0];
    const float* log_w_real = (const float*)d_in[1];
    const float* w_imag     = (const float*)d_in[2];
    const float* C_re       = (const float*)d_in[3];
    const float* C_im       = (const float*)d_in[4];
    float* out = (float*)d_out;

    cudaFuncSetAttribute(ssk_diag_kernel,
                         cudaFuncAttributeMaxDynamicSharedMemorySize, SM_TOTAL);

    ssk_diag_kernel<<<HDIM, 256, SM_TOTAL>>>(log_dt, log_w_real, w_imag,
                                             C_re, C_im, out);
}

// round 16
// speedup vs baseline: 1.1199x; 1.1199x over previous
#include <cuda_runtime.h>
#include <cuda_bf16.h>
#include <cstdint>

// S4D diagonal SSM via split-precision bf16 mma.sync (HMMA).
// Factor l = 64k + j (k in [0,32), j in [0,64)):
//   out[h,64k+j] = sum_n ( Bre[k,n]*Are[n,j] - Bim[k,n]*Aim[n,j] )
// GEMM: D2[64][64] = Bop[64x128] . Aop[64x128]^T,  reduction dim = 2n (re,im)
//   Bop rows 0-31 = bf16_hi(Bre,-Bim), rows 32-63 = bf16_lo residual.
//   A hi/lo tables = accumulating passes; B-lo rows take only the A-hi pass
//   (dropped Bl*Al term ~2^-18). out[64k+j] = D2[k][j] + D2[k+32][j] in registers.
// R16: all fragment loads via ldmatrix.m8n8.x4 (conflict-free: ROWB=272B => 68
//   words = 4 mod 32, so the 8 rows of every 8x8 tile hit disjoint bank quads).
//   4 LDSM per warp-step replaces 16 conflicted LDS.32 + address IMADs.

#define HDIM 1024
#define NDIM 64
#define LLEN 2048

#define ROWB 272      // row stride bytes: 128 bf16 + 8 pad
#define SM_BOP 0                      // 64 x ROWB
#define SM_AH  (64*ROWB)
#define SM_AL  (SM_AH + 64*ROWB)
#define SM_TOTAL (SM_AL + 64*ROWB)    // 52224 B

struct c2 { float re, im; };
__device__ __forceinline__ c2 cmul(c2 a, c2 b) {
    return { fmaf(a.re, b.re, -a.im*b.im), fmaf(a.re, b.im, a.im*b.re) };
}

__device__ __forceinline__ void mma16816(float* c, const uint32_t* a, const uint32_t* b) {
    asm volatile(
        "mma.sync.aligned.m16n8k16.row.col.f32.bf16.bf16.f32 "
        "{%0,%1,%2,%3}, {%4,%5,%6,%7}, {%8,%9}, {%0,%1,%2,%3};"
        : "+f"(c[0]), "+f"(c[1]), "+f"(c[2]), "+f"(c[3])
        : "r"(a[0]), "r"(a[1]), "r"(a[2]), "r"(a[3]), "r"(b[0]), "r"(b[1]));
}

__device__ __forceinline__ void ldsm4(uint32_t& r0, uint32_t& r1, uint32_t& r2,
                                      uint32_t& r3, uint32_t addr) {
    asm volatile("ldmatrix.sync.aligned.m8n8.x4.shared.b16 {%0,%1,%2,%3}, [%4];"
                 : "=r"(r0), "=r"(r1), "=r"(r2), "=r"(r3) : "r"(addr));
}

__global__ __launch_bounds__(256) void ssk_diag_kernel(
    const float* __restrict__ log_dt,
    const float* __restrict__ log_w_real,
    const float* __restrict__ w_imag,
    const float* __restrict__ C_re,
    const float* __restrict__ C_im,
    float* __restrict__ out)
{
    extern __shared__ char smem[];
    const uint32_t smem_base = (uint32_t)__cvta_generic_to_shared(smem);
    const int h   = blockIdx.x;
    const int tid = threadIdx.x;
    const int wid = tid >> 5;
    const int lid = tid & 31;

    // ------------- Phase 1: tables. tid = q*64 + n (4 segments per n) ---------------
    {
        const int n = tid & 63;
        const int q = tid >> 6;     // 0..3

        const float dtv = expf(log_dt[h]);
        const float wre = -expf(log_w_real[h*NDIM + n]);
        const float wim = w_imag[h*NDIM + n];
        const float er  = expf(wre * dtv);
        float s, c; sincosf(wim * dtv, &s, &c);
        const c2 z = { er*c, er*s };

        // cmod = 2 * C * (z - 1) / w  (fold the output factor of 2)
        const float nre = z.re - 1.0f, nim = z.im;
        const float inv = 1.0f / (wre*wre + wim*wim);
        const float tre = (nre*wre + nim*wim) * inv;
        const float tim = (nim*wre - nre*wim) * inv;
        const float cr = C_re[h*NDIM + n], ci = C_im[h*NDIM + n];
        const c2 cm = { 2.0f*(cr*tre - ci*tim), 2.0f*(cr*tim + ci*tre) };

        // power ladder by squaring
        const c2 z2    = cmul(z,    z);
        const c2 z4    = cmul(z2,   z2);
        const c2 z8    = cmul(z4,   z4);
        const c2 z16   = cmul(z8,   z8);
        const c2 z32   = cmul(z16,  z16);
        const c2 z64   = cmul(z32,  z32);
        const c2 z128  = cmul(z64,  z64);
        const c2 z256  = cmul(z128, z128);
        const c2 z512  = cmul(z256, z256);
        const c2 z1024 = cmul(z512, z512);

        // Aop: rows j = 16q .. 16q+15, cols (2n,2n+1) = (Are, Aim); hi + lo residual
        c2 a = {1.0f, 0.0f};
        if (q & 1) a = z16;
        if (q & 2) a = cmul(a, z32);
        #pragma unroll
        for (int jj = 0; jj < 16; jj++) {
            const int j = 16*q + jj;
            const __nv_bfloat16 hr = __float2bfloat16_rn(a.re);
            const __nv_bfloat16 hi = __float2bfloat16_rn(a.im);
            *reinterpret_cast<__nv_bfloat162*>(smem + SM_AH + j*ROWB + 4*n) =
                __nv_bfloat162(hr, hi);
            *reinterpret_cast<__nv_bfloat162*>(smem + SM_AL + j*ROWB + 4*n) =
                __floats2bfloat162_rn(a.re - __bfloat162float(hr),
                                      a.im - __bfloat162float(hi));
            a = cmul(a, z);
        }

        // Bop: rows k = 8q .. 8q+7 (hi) and k+32 (lo), cols = (Bre, -Bim)
        c2 b = cm;
        if (q & 1) b = cmul(b, z512);
        if (q & 2) b = cmul(b, z1024);
        #pragma unroll
        for (int kk = 0; kk < 8; kk++) {
            const int k = 8*q + kk;
            const float bre = b.re, bim = -b.im;
            const __nv_bfloat16 hr = __float2bfloat16_rn(bre);
            const __nv_bfloat16 hi = __float2bfloat16_rn(bim);
            *reinterpret_cast<__nv_bfloat162*>(smem + SM_BOP + k*ROWB + 4*n) =
                __nv_bfloat162(hr, hi);
            *reinterpret_cast<__nv_bfloat162*>(smem + SM_BOP + (k+32)*ROWB + 4*n) =
                __floats2bfloat162_rn(bre - __bfloat162float(hr),
                                      bim - __bfloat162float(hi));
            b = cmul(b, z64);
        }
    }
    __syncthreads();

    // ------------- Phase 2: mma.sync. 8 warps: mw = wid&1, nw = wid>>1 -------------
    const int g  = lid >> 2;    // 0..7
    const int t  = lid & 3;     // 0..3
    const int mw = wid & 1;
    const int nw = wid >> 1;    // 0..3

    // ldmatrix lane roles
    const int tile = lid >> 3;  // 0..3
    const int rit  = lid & 7;   // row in tile

    // A-frag (Bop) tile order: (r,k0),(r+8,k0),(r,k8),(r+8,k8)
    //   row = 16*mw + (tile&1)*8 + rit ; kb = (tile>>1)*16
    uint32_t adr_af_h = smem_base + SM_BOP
        + (uint32_t)(16*mw + ((tile & 1) << 3) + rit) * ROWB + ((tile >> 1) << 4);
    uint32_t adr_af_l = adr_af_h + 32u*ROWB;

    // B-frag (Aop) tile order: (j0-7,k0),(j0-7,k8),(j8-15,k0),(j8-15,k8)
    //   row j = 16*nw + (tile>>1)*8 + rit ; kb = (tile&1)*16
    uint32_t adr_b_h = smem_base + SM_AH
        + (uint32_t)(16*nw + ((tile >> 1) << 3) + rit) * ROWB + ((tile & 1) << 4);
    uint32_t adr_b_l = adr_b_h + (uint32_t)(SM_AL - SM_AH);

    float acc[2][2][4];         // [mt][nt][c]
    #pragma unroll
    for (int mt = 0; mt < 2; mt++)
        #pragma unroll
        for (int nt = 0; nt < 2; nt++)
            #pragma unroll
            for (int i = 0; i < 4; i++) acc[mt][nt][i] = 0.0f;

    #pragma unroll
    for (int s = 0; s < 8; s++) {
        const uint32_t kadd = (uint32_t)s * 32u;   // 16 bf16 per step

        uint32_t afh[4], afl[4], bh[4], bl[4];
        ldsm4(afh[0], afh[1], afh[2], afh[3], adr_af_h + kadd);
        ldsm4(afl[0], afl[1], afl[2], afl[3], adr_af_l + kadd);
        ldsm4(bh[0],  bh[1],  bh[2],  bh[3],  adr_b_h  + kadd);
        ldsm4(bl[0],  bl[1],  bl[2],  bl[3],  adr_b_l  + kadd);

        // b regs: nt=0 -> {r0,r1}; nt=1 -> {r2,r3}
        mma16816(acc[0][0], afh, bh);
        mma16816(acc[0][0], afh, bl);
        mma16816(acc[1][0], afl, bh);
        mma16816(acc[0][1], afh, bh + 2);
        mma16816(acc[0][1], afh, bl + 2);
        mma16816(acc[1][1], afl, bh + 2);
    }

    // ------------- Epilogue: in-register halves add, direct STG.64 ------------------
    // Thread owns D2 rows k = 16mw+g, +8 (hi) and +32 (lo); cols j = 16nw+8nt+2t,+1.
    {
        const int k0 = 16*mw + g;
        float* po = out + (size_t)h*LLEN + 16*nw + 2*t;
        #pragma unroll
        for (int nt = 0; nt < 2; nt++) {
            float2 v0, v1;
            v0.x = acc[0][nt][0] + acc[1][nt][0];
            v0.y = acc[0][nt][1] + acc[1][nt][1];
            v1.x = acc[0][nt][2] + acc[1][nt][2];
            v1.y = acc[0][nt][3] + acc[1][nt][3];
            *reinterpret_cast<float2*>(po + (size_t)k0*64 + 8*nt)     = v0;
            *reinterpret_cast<float2*>(po + (size_t)(k0+8)*64 + 8*nt) = v1;
        }
    }
}

extern "C" void kernel_launch(void* const* d_in, const int* in_sizes, int n_in,
                              void* d_out, int out_size)
{
    const float* log_dt     = (const float*)d_in[0];
    const float* log_w_real = (const float*)d_in[1];
    const float* w_imag     = (const float*)d_in[2];
    const float* C_re       = (const float*)d_in[3];
    const float* C_im       = (const float*)d_in[4];
    float* out = (float*)d_out;

    cudaFuncSetAttribute(ssk_diag_kernel,
                         cudaFuncAttributeMaxDynamicSharedMemorySize, SM_TOTAL);

    ssk_diag_kernel<<<HDIM, 256, SM_TOTAL>>>(log_dt, log_w_real, w_imag,
                                             C_re, C_im, out);
}